// round 12
// baseline (speedup 1.0000x reference)
#include <cuda_runtime.h>
#include <cuda_fp16.h>

#define NMAX 100064
#define EMAX 1600000
#define DD   128

// Scratch (allocation-free)
__device__ float g_dinv[NMAX];
__device__ int   g_cnt[NMAX];
__device__ int   g_rowptr[NMAX];
__device__ int   g_cursor[NMAX];
__device__ int   g_col[EMAX];
__device__ int   g_part[1024];
__device__ __half g_h1[(size_t)NMAX * DD];  // layer-1 pre-scaled GEMM output (fp16)
__device__ __half g_h2[(size_t)NMAX * DD];  // layer-2 pre-scaled GEMM output (fp16)
__device__ float  g_a[(size_t)NMAX * DD];   // layer-1 aggregated output (fp32)
__device__ float g_w1h[DD * DD];
__device__ float g_w1l[DD * DD];
__device__ float g_w2h[DD * DD];
__device__ float g_w2l[DD * DD];

// ---------------------------------------------------------------------------
// Degree / CSR build
// ---------------------------------------------------------------------------
__global__ void k_count(const int* __restrict__ dst, int E) {
    int t = blockIdx.x * blockDim.x + threadIdx.x;
    int e4 = t * 4;
    if (e4 + 4 <= E) {
        int4 d = *(const int4*)(dst + e4);
        atomicAdd(&g_cnt[d.x], 1);
        atomicAdd(&g_cnt[d.y], 1);
        atomicAdd(&g_cnt[d.z], 1);
        atomicAdd(&g_cnt[d.w], 1);
    } else {
        for (int e = e4; e < E; e++) atomicAdd(&g_cnt[dst[e]], 1);
    }
}

// Scan level-1 + fused dinv.
__global__ __launch_bounds__(1024) void k_scan1(int n) {
    const int tid = threadIdx.x;
    const int gid = blockIdx.x * 1024 + tid;
    const int lane = tid & 31, wid = tid >> 5;
    int v = (gid < n) ? g_cnt[gid] : 0;
    if (gid < n) g_dinv[gid] = rsqrtf((float)(v + 1));
    int x = v;
#pragma unroll
    for (int o = 1; o < 32; o <<= 1) {
        int y = __shfl_up_sync(0xffffffffu, x, o);
        if (lane >= o) x += y;
    }
    __shared__ int wsum[32];
    if (lane == 31) wsum[wid] = x;
    __syncthreads();
    if (wid == 0) {
        int s = wsum[lane];
#pragma unroll
        for (int o = 1; o < 32; o <<= 1) {
            int y = __shfl_up_sync(0xffffffffu, s, o);
            if (lane >= o) s += y;
        }
        wsum[lane] = s;
    }
    __syncthreads();
    int incl = x + (wid > 0 ? wsum[wid - 1] : 0);
    if (gid < n) g_rowptr[gid] = incl - v;
    if (tid == 1023) g_part[blockIdx.x] = incl;
}

__global__ __launch_bounds__(1024) void k_scan2(int nb) {
    const int tid = threadIdx.x;
    const int lane = tid & 31, wid = tid >> 5;
    int v = (tid < nb) ? g_part[tid] : 0;
    int x = v;
#pragma unroll
    for (int o = 1; o < 32; o <<= 1) {
        int y = __shfl_up_sync(0xffffffffu, x, o);
        if (lane >= o) x += y;
    }
    __shared__ int wsum[32];
    if (lane == 31) wsum[wid] = x;
    __syncthreads();
    if (wid == 0) {
        int s = wsum[lane];
#pragma unroll
        for (int o = 1; o < 32; o <<= 1) {
            int y = __shfl_up_sync(0xffffffffu, s, o);
            if (lane >= o) s += y;
        }
        wsum[lane] = s;
    }
    __syncthreads();
    int excl = x - v + (wid > 0 ? wsum[wid - 1] : 0);
    if (tid < nb) g_part[tid] = excl;
}

__global__ __launch_bounds__(1024) void k_scan3(int n) {
    int gid = blockIdx.x * 1024 + threadIdx.x;
    if (gid < n) {
        int rp = g_rowptr[gid] + g_part[blockIdx.x];
        g_rowptr[gid] = rp;
        g_cursor[gid] = rp;
    }
}

__global__ void k_scatter(const int* __restrict__ src, const int* __restrict__ dst, int E) {
    int t = blockIdx.x * blockDim.x + threadIdx.x;
    int e4 = t * 4;
    if (e4 + 4 <= E) {
        int4 s = *(const int4*)(src + e4);
        int4 d = *(const int4*)(dst + e4);
        g_col[atomicAdd(&g_cursor[d.x], 1)] = s.x;
        g_col[atomicAdd(&g_cursor[d.y], 1)] = s.y;
        g_col[atomicAdd(&g_cursor[d.z], 1)] = s.z;
        g_col[atomicAdd(&g_cursor[d.w], 1)] = s.w;
    } else {
        for (int e = e4; e < E; e++)
            g_col[atomicAdd(&g_cursor[dst[e]], 1)] = src[e];
    }
}

// ---------------------------------------------------------------------------
// Split W into tf32 hi/lo and transpose
// ---------------------------------------------------------------------------
__global__ void k_split_w(const float* __restrict__ W,
                          float* __restrict__ Wh, float* __restrict__ Wl) {
    int i = blockIdx.x * blockDim.x + threadIdx.x;
    if (i >= DD * DD) return;
    int j = i >> 7, k = i & 127;
    float v = W[j * DD + k];
    unsigned h;
    asm("cvt.rna.tf32.f32 %0, %1;" : "=r"(h) : "f"(v));
    float resid = v - __uint_as_float(h);
    unsigned l;
    asm("cvt.rna.tf32.f32 %0, %1;" : "=r"(l) : "f"(resid));
    Wh[k * DD + j] = __uint_as_float(h);
    Wl[k * DD + j] = __uint_as_float(l);
}

// ---------------------------------------------------------------------------
// Tensor-core GEMM (3xTF32), A-rows pre-scaled by dinv:
//   Y[r,:] (fp16) = dinv[r] * ( X[r,:] @ W^T )
// ---------------------------------------------------------------------------
#define MMA_TF32(C, A, B0, B1)                                                 \
    asm volatile("mma.sync.aligned.m16n8k8.row.col.f32.tf32.tf32.f32 "        \
                 "{%0,%1,%2,%3}, {%4,%5,%6,%7}, {%8,%9}, {%0,%1,%2,%3};"      \
                 : "+f"(C[0]), "+f"(C[1]), "+f"(C[2]), "+f"(C[3])             \
                 : "r"(A[0]), "r"(A[1]), "r"(A[2]), "r"(A[3]), "r"(B0), "r"(B1))

__global__ __launch_bounds__(256) void k_gemm_tc(const float* __restrict__ X,
                                                 const float* __restrict__ Wth,
                                                 const float* __restrict__ Wtl,
                                                 __half* __restrict__ Y,
                                                 int rbase, int n) {
    __shared__ float xs[128][36];
    __shared__ float wh[32][136];
    __shared__ float wl[32][136];

    const int tid  = threadIdx.x;
    const int warp = tid >> 5;
    const int lane = tid & 31;
    const int g    = lane >> 2;
    const int tig  = lane & 3;
    const int br   = rbase + blockIdx.x * 128;
    const int rb   = warp * 16;

    float c[16][4];
#pragma unroll
    for (int nt = 0; nt < 16; nt++)
#pragma unroll
        for (int q = 0; q < 4; q++) c[nt][q] = 0.0f;

    for (int kc = 0; kc < 128; kc += 32) {
#pragma unroll
        for (int j = 0; j < 4; j++) {
            int i = tid + j * 256;
            int r = i >> 3, kq = (i & 7) * 4;
            int row = br + r;
            float4 v = make_float4(0.f, 0.f, 0.f, 0.f);
            if (row < n) {
                float sc = g_dinv[row];
                v = *(const float4*)&X[(size_t)row * 128 + kc + kq];
                v.x *= sc; v.y *= sc; v.z *= sc; v.w *= sc;
            }
            *(float4*)&xs[r][kq] = v;
        }
#pragma unroll
        for (int j = 0; j < 4; j++) {
            int i = tid + j * 256;
            int k = i >> 5, jq = (i & 31) * 4;
            *(float4*)&wh[k][jq] = *(const float4*)&Wth[(kc + k) * 128 + jq];
            *(float4*)&wl[k][jq] = *(const float4*)&Wtl[(kc + k) * 128 + jq];
        }
        __syncthreads();

#pragma unroll
        for (int ks = 0; ks < 32; ks += 8) {
            float a_raw[4];
            a_raw[0] = xs[rb + g][ks + tig];
            a_raw[1] = xs[rb + g + 8][ks + tig];
            a_raw[2] = xs[rb + g][ks + tig + 4];
            a_raw[3] = xs[rb + g + 8][ks + tig + 4];
            unsigned ah[4], al[4];
#pragma unroll
            for (int q = 0; q < 4; q++) {
                asm("cvt.rna.tf32.f32 %0, %1;" : "=r"(ah[q]) : "f"(a_raw[q]));
                float resid = a_raw[q] - __uint_as_float(ah[q]);
                asm("cvt.rna.tf32.f32 %0, %1;" : "=r"(al[q]) : "f"(resid));
            }
#pragma unroll
            for (int nt = 0; nt < 16; nt++) {
                int col = nt * 8 + g;
                unsigned bh0 = __float_as_uint(wh[ks + tig][col]);
                unsigned bh1 = __float_as_uint(wh[ks + tig + 4][col]);
                unsigned bl0 = __float_as_uint(wl[ks + tig][col]);
                unsigned bl1 = __float_as_uint(wl[ks + tig + 4][col]);
                MMA_TF32(c[nt], ah, bh0, bh1);
                MMA_TF32(c[nt], al, bh0, bh1);
                MMA_TF32(c[nt], ah, bl0, bl1);
            }
        }
        __syncthreads();
    }

    const int row0 = br + rb + g;
    const int row1 = row0 + 8;
#pragma unroll
    for (int nt = 0; nt < 16; nt++) {
        int col = nt * 8 + tig * 2;
        if (row0 < n)
            *(__half2*)&Y[(size_t)row0 * 128 + col] = __floats2half2_rn(c[nt][0], c[nt][1]);
        if (row1 < n)
            *(__half2*)&Y[(size_t)row1 * 128 + col] = __floats2half2_rn(c[nt][2], c[nt][3]);
    }
}

// ---------------------------------------------------------------------------
// Gather aggregation over pre-scaled rows H' = dinv .* H:
//   O[d,:] = dinv[d] * ( H'[d,:] + sum_{s in N(d)} H'[s,:] ) + bias + P[d,:]
// One warp per node; lane owns 4 columns; 8-deep independent load batches.
// ---------------------------------------------------------------------------
__device__ __forceinline__ float4 ld_row_h4(const __half* __restrict__ H, int s, int lane) {
    uint2 u = *(const uint2*)(H + (size_t)s * 128 + lane * 4);
    float2 f0 = __half22float2(*(__half2*)&u.x);
    float2 f1 = __half22float2(*(__half2*)&u.y);
    return make_float4(f0.x, f0.y, f1.x, f1.y);
}

__global__ __launch_bounds__(256) void k_gather(const __half* __restrict__ H,
                                                const float* __restrict__ bias,
                                                const float4* __restrict__ P,
                                                float4* __restrict__ O,
                                                int off, int nchunk) {
    int w = (blockIdx.x * blockDim.x + threadIdx.x) >> 5;
    if (w >= nchunk) return;
    const int lane = threadIdx.x & 31;
    const int d = off + w;

    float4 acc = ld_row_h4(H, d, lane);   // self term (pre-scaled)

    const int start = g_rowptr[d];
    const int cnt   = g_cnt[d];

    for (int base = 0; base < cnt; base += 32) {
        int m = cnt - base; if (m > 32) m = 32;
        int idx = (lane < m) ? __ldg(&g_col[start + base + lane]) : 0;
        int k = 0;
        for (; k + 8 <= m; k += 8) {
            int s[8];
            float4 v[8];
#pragma unroll
            for (int q = 0; q < 8; q++) s[q] = __shfl_sync(0xffffffffu, idx, k + q);
#pragma unroll
            for (int q = 0; q < 8; q++) v[q] = ld_row_h4(H, s[q], lane);
#pragma unroll
            for (int q = 0; q < 8; q++) {
                acc.x += v[q].x; acc.y += v[q].y; acc.z += v[q].z; acc.w += v[q].w;
            }
        }
        for (; k < m; k++) {
            int s0 = __shfl_sync(0xffffffffu, idx, k);
            float4 v0 = ld_row_h4(H, s0, lane);
            acc.x += v0.x; acc.y += v0.y; acc.z += v0.z; acc.w += v0.w;
        }
    }

    const float dd = g_dinv[d];
    float4 b4 = ((const float4*)bias)[lane];
    float4 p  = P[(size_t)d * 32 + lane];
    float4 o;
    o.x = dd * acc.x + b4.x + p.x;
    o.y = dd * acc.y + b4.y + p.y;
    o.z = dd * acc.z + b4.z + p.z;
    o.w = dd * acc.w + b4.w + p.w;
    O[(size_t)d * 32 + lane] = o;
}

// ---------------------------------------------------------------------------
// Launch
// ---------------------------------------------------------------------------
extern "C" void kernel_launch(void* const* d_in, const int* in_sizes, int n_in,
                              void* d_out, int out_size) {
    const float* x  = (const float*)d_in[0];
    const int*   ei = (const int*)  d_in[1];
    const float* pf = (const float*)d_in[2];
    const float* pl = (const float*)d_in[3];
    const float* W1 = (const float*)d_in[4];
    const float* b1 = (const float*)d_in[5];
    const float* W2 = (const float*)d_in[6];
    const float* b2 = (const float*)d_in[7];
    float* out = (float*)d_out;

    const int n = in_sizes[0] / DD;
    const int E = in_sizes[1] / 2;
    const int* src = ei;
    const int* dst = ei + E;

    __half* ph1; __half* ph2; float* pa; int* pcnt;
    float* w1h; float* w1l; float* w2h; float* w2l;
    cudaGetSymbolAddress((void**)&ph1, g_h1);
    cudaGetSymbolAddress((void**)&ph2, g_h2);
    cudaGetSymbolAddress((void**)&pa, g_a);
    cudaGetSymbolAddress((void**)&pcnt, g_cnt);
    cudaGetSymbolAddress((void**)&w1h, g_w1h);
    cudaGetSymbolAddress((void**)&w1l, g_w1l);
    cudaGetSymbolAddress((void**)&w2h, g_w2h);
    cudaGetSymbolAddress((void**)&w2l, g_w2l);

    static cudaStream_t s2 = nullptr;
    static cudaEvent_t evFork = nullptr, evDinv = nullptr, evJoin = nullptr,
                       evA = nullptr, evG2A = nullptr;
    if (!s2) {
        cudaStreamCreateWithFlags(&s2, cudaStreamNonBlocking);
        cudaEventCreateWithFlags(&evFork, cudaEventDisableTiming);
        cudaEventCreateWithFlags(&evDinv, cudaEventDisableTiming);
        cudaEventCreateWithFlags(&evJoin, cudaEventDisableTiming);
        cudaEventCreateWithFlags(&evA, cudaEventDisableTiming);
        cudaEventCreateWithFlags(&evG2A, cudaEventDisableTiming);
    }

    const int T = 256;
    const int nb1024 = (n + 1023) / 1024;
    const int splitw_blocks = (DD * DD + T - 1) / T;
    const int e4blocks = ((E + 3) / 4 + T - 1) / T;

    const int nA = (((n + 1) / 2 + 127) / 128) * 128;
    const int nB = n - nA;

    // Fork: side stream pre-splits W1/W2 (no deps).
    cudaEventRecord(evFork, 0);
    cudaStreamWaitEvent(s2, evFork, 0);
    k_split_w<<<splitw_blocks, T, 0, s2>>>(W1, w1h, w1l);
    k_split_w<<<splitw_blocks, T, 0, s2>>>(W2, w2h, w2l);

    // Main: degrees + dinv.
    cudaMemsetAsync(pcnt, 0, (size_t)n * sizeof(int), 0);
    k_count<<<e4blocks, T>>>(dst, E);
    k_scan1<<<nb1024, 1024>>>(n);   // dinv ready after this
    cudaEventRecord(evDinv, 0);

    // Side: gemm1 -> h1 (scaled rows), concurrent with scan2/scan3/scatter.
    cudaStreamWaitEvent(s2, evDinv, 0);
    k_gemm_tc<<<(n + 127) / 128, T, 0, s2>>>(x, w1h, w1l, ph1, 0, n);
    cudaEventRecord(evJoin, s2);

    // Main: finish CSR.
    k_scan2<<<1, 1024>>>(nb1024);
    k_scan3<<<nb1024, 1024>>>(n);
    k_scatter<<<e4blocks, T>>>(src, dst, E);

    cudaStreamWaitEvent(0, evJoin, 0);

    // gather1(A) reads h1 -> pa[A]; gemm2(A) reads pa[A] -> h2[A] on s2,
    // overlapped with gather1(B) which reads h1 (h1 is never overwritten).
    k_gather<<<(nA + 7) / 8, T>>>(ph1, b1, (const float4*)pf, (float4*)pa, 0, nA);
    cudaEventRecord(evA, 0);
    cudaStreamWaitEvent(s2, evA, 0);
    k_gemm_tc<<<nA / 128, T, 0, s2>>>(pa, w2h, w2l, ph2, 0, nA);
    cudaEventRecord(evG2A, s2);

    k_gather<<<(nB + 7) / 8, T>>>(ph1, b1, (const float4*)pf, (float4*)pa, nA, nB);
    k_gemm_tc<<<(nB + 127) / 128, T>>>(pa, w2h, w2l, ph2, nA, n);
    cudaStreamWaitEvent(0, evG2A, 0);

    // Final gather over all nodes reads h2.
    k_gather<<<(n + 7) / 8, T>>>(ph2, b2, (const float4*)pl, (float4*)out, 0, n);
}

// round 14
// speedup vs baseline: 1.0136x; 1.0136x over previous
#include <cuda_runtime.h>
#include <cuda_fp16.h>

#define NMAX 100064
#define EMAX 1600000
#define DD   128

// Scratch (allocation-free). g_cnt is zero at module load; each launch re-zeros
// it after its last read (k_scan1), so every call sees zeros deterministically.
__device__ float g_dinv[NMAX];
__device__ int   g_cnt[NMAX];
__device__ int   g_rowptr[NMAX + 1];
__device__ int   g_cursor[NMAX];
__device__ int   g_col[EMAX];
__device__ int   g_part[1024];
__device__ __half g_h1[(size_t)NMAX * DD];  // layer-1 pre-scaled GEMM output (fp16)
__device__ __half g_h2[(size_t)NMAX * DD];  // layer-2 pre-scaled GEMM output (fp16)
__device__ float  g_a[(size_t)NMAX * DD];   // layer-1 aggregated output (fp32)
__device__ float g_w1h[DD * DD];
__device__ float g_w1l[DD * DD];
__device__ float g_w2h[DD * DD];
__device__ float g_w2l[DD * DD];

// ---------------------------------------------------------------------------
// Degree / CSR build
// ---------------------------------------------------------------------------
__global__ void k_count(const int* __restrict__ dst, int E) {
    int t = blockIdx.x * blockDim.x + threadIdx.x;
    int e4 = t * 4;
    if (e4 + 4 <= E) {
        int4 d = *(const int4*)(dst + e4);
        atomicAdd(&g_cnt[d.x], 1);
        atomicAdd(&g_cnt[d.y], 1);
        atomicAdd(&g_cnt[d.z], 1);
        atomicAdd(&g_cnt[d.w], 1);
    } else {
        for (int e = e4; e < E; e++) atomicAdd(&g_cnt[dst[e]], 1);
    }
}

__global__ void k_zero_cnt(int n) {
    int i = blockIdx.x * blockDim.x + threadIdx.x;
    if (i < n) g_cnt[i] = 0;
}

// Scan level-1 + fused dinv (last reader of g_cnt).
__global__ __launch_bounds__(1024) void k_scan1(int n) {
    const int tid = threadIdx.x;
    const int gid = blockIdx.x * 1024 + tid;
    const int lane = tid & 31, wid = tid >> 5;
    int v = (gid < n) ? g_cnt[gid] : 0;
    if (gid < n) g_dinv[gid] = rsqrtf((float)(v + 1));
    int x = v;
#pragma unroll
    for (int o = 1; o < 32; o <<= 1) {
        int y = __shfl_up_sync(0xffffffffu, x, o);
        if (lane >= o) x += y;
    }
    __shared__ int wsum[32];
    if (lane == 31) wsum[wid] = x;
    __syncthreads();
    if (wid == 0) {
        int s = wsum[lane];
#pragma unroll
        for (int o = 1; o < 32; o <<= 1) {
            int y = __shfl_up_sync(0xffffffffu, s, o);
            if (lane >= o) s += y;
        }
        wsum[lane] = s;
    }
    __syncthreads();
    int incl = x + (wid > 0 ? wsum[wid - 1] : 0);
    if (gid < n) g_rowptr[gid] = incl - v;
    if (tid == 1023) g_part[blockIdx.x] = incl;
}

__global__ __launch_bounds__(1024) void k_scan2(int nb) {
    const int tid = threadIdx.x;
    const int lane = tid & 31, wid = tid >> 5;
    int v = (tid < nb) ? g_part[tid] : 0;
    int x = v;
#pragma unroll
    for (int o = 1; o < 32; o <<= 1) {
        int y = __shfl_up_sync(0xffffffffu, x, o);
        if (lane >= o) x += y;
    }
    __shared__ int wsum[32];
    if (lane == 31) wsum[wid] = x;
    __syncthreads();
    if (wid == 0) {
        int s = wsum[lane];
#pragma unroll
        for (int o = 1; o < 32; o <<= 1) {
            int y = __shfl_up_sync(0xffffffffu, s, o);
            if (lane >= o) s += y;
        }
        wsum[lane] = s;
    }
    __syncthreads();
    int excl = x - v + (wid > 0 ? wsum[wid - 1] : 0);
    if (tid < nb) g_part[tid] = excl;
}

__global__ __launch_bounds__(1024) void k_scan3(int n, int E) {
    int gid = blockIdx.x * 1024 + threadIdx.x;
    if (gid < n) {
        int rp = g_rowptr[gid] + g_part[blockIdx.x];
        g_rowptr[gid] = rp;
        g_cursor[gid] = rp;
    } else if (gid == n) {
        g_rowptr[n] = E;
    }
}

__global__ void k_scatter(const int* __restrict__ src, const int* __restrict__ dst, int E) {
    int t = blockIdx.x * blockDim.x + threadIdx.x;
    int e4 = t * 4;
    if (e4 + 4 <= E) {
        int4 s = *(const int4*)(src + e4);
        int4 d = *(const int4*)(dst + e4);
        g_col[atomicAdd(&g_cursor[d.x], 1)] = s.x;
        g_col[atomicAdd(&g_cursor[d.y], 1)] = s.y;
        g_col[atomicAdd(&g_cursor[d.z], 1)] = s.z;
        g_col[atomicAdd(&g_cursor[d.w], 1)] = s.w;
    } else {
        for (int e = e4; e < E; e++)
            g_col[atomicAdd(&g_cursor[dst[e]], 1)] = src[e];
    }
}

// ---------------------------------------------------------------------------
// Split W into tf32 hi/lo and transpose
// ---------------------------------------------------------------------------
__global__ void k_split_w(const float* __restrict__ W,
                          float* __restrict__ Wh, float* __restrict__ Wl) {
    int i = blockIdx.x * blockDim.x + threadIdx.x;
    if (i >= DD * DD) return;
    int j = i >> 7, k = i & 127;
    float v = W[j * DD + k];
    unsigned h;
    asm("cvt.rna.tf32.f32 %0, %1;" : "=r"(h) : "f"(v));
    float resid = v - __uint_as_float(h);
    unsigned l;
    asm("cvt.rna.tf32.f32 %0, %1;" : "=r"(l) : "f"(resid));
    Wh[k * DD + j] = __uint_as_float(h);
    Wl[k * DD + j] = __uint_as_float(l);
}

// ---------------------------------------------------------------------------
// Tensor-core GEMM (3xTF32), A-rows pre-scaled by dinv:
//   Y[r,:] (fp16) = dinv[r] * ( X[r,:] @ W^T )
// ---------------------------------------------------------------------------
#define MMA_TF32(C, A, B0, B1)                                                 \
    asm volatile("mma.sync.aligned.m16n8k8.row.col.f32.tf32.tf32.f32 "        \
                 "{%0,%1,%2,%3}, {%4,%5,%6,%7}, {%8,%9}, {%0,%1,%2,%3};"      \
                 : "+f"(C[0]), "+f"(C[1]), "+f"(C[2]), "+f"(C[3])             \
                 : "r"(A[0]), "r"(A[1]), "r"(A[2]), "r"(A[3]), "r"(B0), "r"(B1))

__global__ __launch_bounds__(256) void k_gemm_tc(const float* __restrict__ X,
                                                 const float* __restrict__ Wth,
                                                 const float* __restrict__ Wtl,
                                                 __half* __restrict__ Y,
                                                 int rbase, int n) {
    __shared__ float xs[128][36];
    __shared__ float wh[32][136];
    __shared__ float wl[32][136];

    const int tid  = threadIdx.x;
    const int warp = tid >> 5;
    const int lane = tid & 31;
    const int g    = lane >> 2;
    const int tig  = lane & 3;
    const int br   = rbase + blockIdx.x * 128;
    const int rb   = warp * 16;

    float c[16][4];
#pragma unroll
    for (int nt = 0; nt < 16; nt++)
#pragma unroll
        for (int q = 0; q < 4; q++) c[nt][q] = 0.0f;

    for (int kc = 0; kc < 128; kc += 32) {
#pragma unroll
        for (int j = 0; j < 4; j++) {
            int i = tid + j * 256;
            int r = i >> 3, kq = (i & 7) * 4;
            int row = br + r;
            float4 v = make_float4(0.f, 0.f, 0.f, 0.f);
            if (row < n) {
                float sc = g_dinv[row];
                v = *(const float4*)&X[(size_t)row * 128 + kc + kq];
                v.x *= sc; v.y *= sc; v.z *= sc; v.w *= sc;
            }
            *(float4*)&xs[r][kq] = v;
        }
#pragma unroll
        for (int j = 0; j < 4; j++) {
            int i = tid + j * 256;
            int k = i >> 5, jq = (i & 31) * 4;
            *(float4*)&wh[k][jq] = *(const float4*)&Wth[(kc + k) * 128 + jq];
            *(float4*)&wl[k][jq] = *(const float4*)&Wtl[(kc + k) * 128 + jq];
        }
        __syncthreads();

#pragma unroll
        for (int ks = 0; ks < 32; ks += 8) {
            float a_raw[4];
            a_raw[0] = xs[rb + g][ks + tig];
            a_raw[1] = xs[rb + g + 8][ks + tig];
            a_raw[2] = xs[rb + g][ks + tig + 4];
            a_raw[3] = xs[rb + g + 8][ks + tig + 4];
            unsigned ah[4], al[4];
#pragma unroll
            for (int q = 0; q < 4; q++) {
                asm("cvt.rna.tf32.f32 %0, %1;" : "=r"(ah[q]) : "f"(a_raw[q]));
                float resid = a_raw[q] - __uint_as_float(ah[q]);
                asm("cvt.rna.tf32.f32 %0, %1;" : "=r"(al[q]) : "f"(resid));
            }
#pragma unroll
            for (int nt = 0; nt < 16; nt++) {
                int col = nt * 8 + g;
                unsigned bh0 = __float_as_uint(wh[ks + tig][col]);
                unsigned bh1 = __float_as_uint(wh[ks + tig + 4][col]);
                unsigned bl0 = __float_as_uint(wl[ks + tig][col]);
                unsigned bl1 = __float_as_uint(wl[ks + tig + 4][col]);
                MMA_TF32(c[nt], ah, bh0, bh1);
                MMA_TF32(c[nt], al, bh0, bh1);
                MMA_TF32(c[nt], ah, bl0, bl1);
            }
        }
        __syncthreads();
    }

    const int row0 = br + rb + g;
    const int row1 = row0 + 8;
#pragma unroll
    for (int nt = 0; nt < 16; nt++) {
        int col = nt * 8 + tig * 2;
        if (row0 < n)
            *(__half2*)&Y[(size_t)row0 * 128 + col] = __floats2half2_rn(c[nt][0], c[nt][1]);
        if (row1 < n)
            *(__half2*)&Y[(size_t)row1 * 128 + col] = __floats2half2_rn(c[nt][2], c[nt][3]);
    }
}

// ---------------------------------------------------------------------------
// Gather: 2 nodes per warp (16 lanes each), LDG.128 payload (16B fp16/lane).
//   O[d,:] = dinv[d] * ( H'[d,:] + sum_{s in N(d)} H'[s,:] ) + bias + P[d,:]
// ---------------------------------------------------------------------------
__device__ __forceinline__ void acc_u4(uint4 u, float acc[8]) {
    const __half2* hp = (const __half2*)&u;
#pragma unroll
    for (int j = 0; j < 4; j++) {
        float2 f = __half22float2(hp[j]);
        acc[2 * j]     += f.x;
        acc[2 * j + 1] += f.y;
    }
}

__global__ __launch_bounds__(256) void k_gather(const __half* __restrict__ H,
                                                const float* __restrict__ bias,
                                                const float4* __restrict__ P,
                                                float4* __restrict__ O,
                                                int off, int nchunk) {
    const int w    = (blockIdx.x * blockDim.x + threadIdx.x) >> 5;
    const int lane = threadIdx.x & 31;
    const int half = lane >> 4;
    const int sl   = lane & 15;
    const int d    = off + w * 2 + half;
    if (d >= off + nchunk) return;
    const unsigned hmask = 0xFFFFu << (half << 4);

    float acc[8];
    {
        uint4 u = *(const uint4*)(H + (size_t)d * 128 + sl * 8);
        const __half2* hp = (const __half2*)&u;
#pragma unroll
        for (int j = 0; j < 4; j++) {
            float2 f = __half22float2(hp[j]);
            acc[2 * j] = f.x; acc[2 * j + 1] = f.y;
        }
    }

    const int rp0 = __ldg(&g_rowptr[d]);
    const int cnt = __ldg(&g_rowptr[d + 1]) - rp0;

    for (int base = 0; base < cnt; base += 16) {
        int m = cnt - base; if (m > 16) m = 16;
        int idx = (sl < m) ? __ldg(&g_col[rp0 + base + sl]) : 0;
        int k = 0;
        for (; k + 8 <= m; k += 8) {
            int s[8]; uint4 u[8];
#pragma unroll
            for (int q = 0; q < 8; q++) s[q] = __shfl_sync(hmask, idx, k + q, 16);
#pragma unroll
            for (int q = 0; q < 8; q++) u[q] = *(const uint4*)(H + (size_t)s[q] * 128 + sl * 8);
#pragma unroll
            for (int q = 0; q < 8; q++) acc_u4(u[q], acc);
        }
        for (; k < m; k++) {
            int s0 = __shfl_sync(hmask, idx, k, 16);
            uint4 u = *(const uint4*)(H + (size_t)s0 * 128 + sl * 8);
            acc_u4(u, acc);
        }
    }

    const float dd = g_dinv[d];
    float4 b0 = ((const float4*)bias)[sl * 2];
    float4 b1 = ((const float4*)bias)[sl * 2 + 1];
    float4 p0 = P[(size_t)d * 32 + sl * 2];
    float4 p1 = P[(size_t)d * 32 + sl * 2 + 1];
    float4 o0, o1;
    o0.x = dd * acc[0] + b0.x + p0.x;
    o0.y = dd * acc[1] + b0.y + p0.y;
    o0.z = dd * acc[2] + b0.z + p0.z;
    o0.w = dd * acc[3] + b0.w + p0.w;
    o1.x = dd * acc[4] + b1.x + p1.x;
    o1.y = dd * acc[5] + b1.y + p1.y;
    o1.z = dd * acc[6] + b1.z + p1.z;
    o1.w = dd * acc[7] + b1.w + p1.w;
    O[(size_t)d * 32 + sl * 2]     = o0;
    O[(size_t)d * 32 + sl * 2 + 1] = o1;
}

// ---------------------------------------------------------------------------
// Launch
// ---------------------------------------------------------------------------
extern "C" void kernel_launch(void* const* d_in, const int* in_sizes, int n_in,
                              void* d_out, int out_size) {
    const float* x  = (const float*)d_in[0];
    const int*   ei = (const int*)  d_in[1];
    const float* pf = (const float*)d_in[2];
    const float* pl = (const float*)d_in[3];
    const float* W1 = (const float*)d_in[4];
    const float* b1 = (const float*)d_in[5];
    const float* W2 = (const float*)d_in[6];
    const float* b2 = (const float*)d_in[7];
    float* out = (float*)d_out;

    const int n = in_sizes[0] / DD;
    const int E = in_sizes[1] / 2;
    const int* src = ei;
    const int* dst = ei + E;

    __half* ph1; __half* ph2; float* pa;
    float* w1h; float* w1l; float* w2h; float* w2l;
    cudaGetSymbolAddress((void**)&ph1, g_h1);
    cudaGetSymbolAddress((void**)&ph2, g_h2);
    cudaGetSymbolAddress((void**)&pa, g_a);
    cudaGetSymbolAddress((void**)&w1h, g_w1h);
    cudaGetSymbolAddress((void**)&w1l, g_w1l);
    cudaGetSymbolAddress((void**)&w2h, g_w2h);
    cudaGetSymbolAddress((void**)&w2l, g_w2l);

    static cudaStream_t s2 = nullptr;
    static cudaEvent_t evFork = nullptr, evDinv = nullptr, evJoin = nullptr,
                       evA = nullptr, evG2A = nullptr;
    if (!s2) {
        cudaStreamCreateWithFlags(&s2, cudaStreamNonBlocking);
        cudaEventCreateWithFlags(&evFork, cudaEventDisableTiming);
        cudaEventCreateWithFlags(&evDinv, cudaEventDisableTiming);
        cudaEventCreateWithFlags(&evJoin, cudaEventDisableTiming);
        cudaEventCreateWithFlags(&evA, cudaEventDisableTiming);
        cudaEventCreateWithFlags(&evG2A, cudaEventDisableTiming);
    }

    const int T = 256;
    const int nb1024 = (n + 1023) / 1024;
    const int splitw_blocks = (DD * DD + T - 1) / T;
    const int e4blocks = ((E + 3) / 4 + T - 1) / T;

    const int nA = (((n + 1) / 2 + 127) / 128) * 128;
    const int nB = n - nA;

    // Fork: side stream pre-splits W1/W2 (no deps).
    cudaEventRecord(evFork, 0);
    cudaStreamWaitEvent(s2, evFork, 0);
    k_split_w<<<splitw_blocks, T, 0, s2>>>(W1, w1h, w1l);
    k_split_w<<<splitw_blocks, T, 0, s2>>>(W2, w2h, w2l);

    // Main: degrees + dinv (g_cnt is zero from module load / previous call).
    k_count<<<e4blocks, T>>>(dst, E);
    k_scan1<<<nb1024, 1024>>>(n);   // dinv + tile-local rowptr; last read of cnt
    cudaEventRecord(evDinv, 0);

    // Side: gemm1 -> h1 (scaled rows), concurrent with rest of CSR build.
    cudaStreamWaitEvent(s2, evDinv, 0);
    k_gemm_tc<<<(n + 127) / 128, T, 0, s2>>>(x, w1h, w1l, ph1, 0, n);
    cudaEventRecord(evJoin, s2);

    // Main: re-zero cnt for next call; finish CSR.
    k_zero_cnt<<<(n + T - 1) / T, T>>>(n);
    k_scan2<<<1, 1024>>>(nb1024);
    k_scan3<<<(n + 1 + 1023) / 1024, 1024>>>(n, E);
    k_scatter<<<e4blocks, T>>>(src, dst, E);

    cudaStreamWaitEvent(0, evJoin, 0);

    // gather1(A) -> pa[A]; gemm2(A): pa[A] -> h2[A] on s2, overlapped with
    // gather1(B) (reads h1, which is never overwritten).
    k_gather<<<(nA + 15) / 16, T>>>(ph1, b1, (const float4*)pf, (float4*)pa, 0, nA);
    cudaEventRecord(evA, 0);
    cudaStreamWaitEvent(s2, evA, 0);
    k_gemm_tc<<<nA / 128, T, 0, s2>>>(pa, w2h, w2l, ph2, 0, nA);
    cudaEventRecord(evG2A, s2);

    k_gather<<<(nB + 15) / 16, T>>>(ph1, b1, (const float4*)pf, (float4*)pa, nA, nB);
    k_gemm_tc<<<(nB + 127) / 128, T>>>(pa, w2h, w2l, ph2, nA, n);
    cudaStreamWaitEvent(0, evG2A, 0);

    // Final gather over all nodes reads h2.
    k_gather<<<(n + 15) / 16, T>>>(ph2, b2, (const float4*)pl, (float4*)out, 0, n);
}

// round 15
// speedup vs baseline: 1.3434x; 1.3254x over previous
#include <cuda_runtime.h>
#include <cuda_fp16.h>
#include <cuda_bf16.h>

#define NMAX 100064
#define EMAX 1600000
#define DD   128

// Scratch (allocation-free). g_cnt is zero at module load; each launch re-zeros
// it after its last read (k_scan1), so every call sees zeros deterministically.
__device__ float g_dinv[NMAX];
__device__ int   g_cnt[NMAX];
__device__ int   g_rowptr[NMAX + 1];
__device__ int   g_cursor[NMAX];
__device__ int   g_col[EMAX];
__device__ int   g_part[1024];
__device__ __half g_h1[(size_t)NMAX * DD];  // layer-1 pre-scaled GEMM output (fp16)
__device__ __half g_h2[(size_t)NMAX * DD];  // layer-2 pre-scaled GEMM output (fp16)
__device__ float  g_a[(size_t)NMAX * DD];   // layer-1 aggregated output (fp32)
// W^T split to bf16 hi/lo, packed as bf16x2 k-pairs: [kpair][j], kpair=k/2.
__device__ unsigned g_w1h[(DD / 2) * DD];
__device__ unsigned g_w1l[(DD / 2) * DD];
__device__ unsigned g_w2h[(DD / 2) * DD];
__device__ unsigned g_w2l[(DD / 2) * DD];

// ---------------------------------------------------------------------------
// Degree / CSR build
// ---------------------------------------------------------------------------
__global__ void k_count(const int* __restrict__ dst, int E) {
    int t = blockIdx.x * blockDim.x + threadIdx.x;
    int e4 = t * 4;
    if (e4 + 4 <= E) {
        int4 d = *(const int4*)(dst + e4);
        atomicAdd(&g_cnt[d.x], 1);
        atomicAdd(&g_cnt[d.y], 1);
        atomicAdd(&g_cnt[d.z], 1);
        atomicAdd(&g_cnt[d.w], 1);
    } else {
        for (int e = e4; e < E; e++) atomicAdd(&g_cnt[dst[e]], 1);
    }
}

__global__ void k_zero_cnt(int n) {
    int i = blockIdx.x * blockDim.x + threadIdx.x;
    if (i < n) g_cnt[i] = 0;
}

// Scan level-1 + fused dinv (last reader of g_cnt).
__global__ __launch_bounds__(1024) void k_scan1(int n) {
    const int tid = threadIdx.x;
    const int gid = blockIdx.x * 1024 + tid;
    const int lane = tid & 31, wid = tid >> 5;
    int v = (gid < n) ? g_cnt[gid] : 0;
    if (gid < n) g_dinv[gid] = rsqrtf((float)(v + 1));
    int x = v;
#pragma unroll
    for (int o = 1; o < 32; o <<= 1) {
        int y = __shfl_up_sync(0xffffffffu, x, o);
        if (lane >= o) x += y;
    }
    __shared__ int wsum[32];
    if (lane == 31) wsum[wid] = x;
    __syncthreads();
    if (wid == 0) {
        int s = wsum[lane];
#pragma unroll
        for (int o = 1; o < 32; o <<= 1) {
            int y = __shfl_up_sync(0xffffffffu, s, o);
            if (lane >= o) s += y;
        }
        wsum[lane] = s;
    }
    __syncthreads();
    int incl = x + (wid > 0 ? wsum[wid - 1] : 0);
    if (gid < n) g_rowptr[gid] = incl - v;
    if (tid == 1023) g_part[blockIdx.x] = incl;
}

__global__ __launch_bounds__(1024) void k_scan2(int nb) {
    const int tid = threadIdx.x;
    const int lane = tid & 31, wid = tid >> 5;
    int v = (tid < nb) ? g_part[tid] : 0;
    int x = v;
#pragma unroll
    for (int o = 1; o < 32; o <<= 1) {
        int y = __shfl_up_sync(0xffffffffu, x, o);
        if (lane >= o) x += y;
    }
    __shared__ int wsum[32];
    if (lane == 31) wsum[wid] = x;
    __syncthreads();
    if (wid == 0) {
        int s = wsum[lane];
#pragma unroll
        for (int o = 1; o < 32; o <<= 1) {
            int y = __shfl_up_sync(0xffffffffu, s, o);
            if (lane >= o) s += y;
        }
        wsum[lane] = s;
    }
    __syncthreads();
    int excl = x - v + (wid > 0 ? wsum[wid - 1] : 0);
    if (tid < nb) g_part[tid] = excl;
}

__global__ __launch_bounds__(1024) void k_scan3(int n, int E) {
    int gid = blockIdx.x * 1024 + threadIdx.x;
    if (gid < n) {
        int rp = g_rowptr[gid] + g_part[blockIdx.x];
        g_rowptr[gid] = rp;
        g_cursor[gid] = rp;
    } else if (gid == n) {
        g_rowptr[n] = E;
    }
}

__global__ void k_scatter(const int* __restrict__ src, const int* __restrict__ dst, int E) {
    int t = blockIdx.x * blockDim.x + threadIdx.x;
    int e4 = t * 4;
    if (e4 + 4 <= E) {
        int4 s = *(const int4*)(src + e4);
        int4 d = *(const int4*)(dst + e4);
        g_col[atomicAdd(&g_cursor[d.x], 1)] = s.x;
        g_col[atomicAdd(&g_cursor[d.y], 1)] = s.y;
        g_col[atomicAdd(&g_cursor[d.z], 1)] = s.z;
        g_col[atomicAdd(&g_cursor[d.w], 1)] = s.w;
    } else {
        for (int e = e4; e < E; e++)
            g_col[atomicAdd(&g_cursor[dst[e]], 1)] = src[e];
    }
}

// ---------------------------------------------------------------------------
// Split W into bf16 hi/lo, transpose, pack k-pairs:
//   out[kp*128 + j] = bf16x2( Wt[2kp][j], Wt[2kp+1][j] ),  Wt[k][j] = W[j][k]
// ---------------------------------------------------------------------------
__global__ void k_split_w(const float* __restrict__ W,
                          unsigned* __restrict__ Wh, unsigned* __restrict__ Wl) {
    int i = blockIdx.x * blockDim.x + threadIdx.x;
    if (i >= (DD / 2) * DD) return;
    int kp = i >> 7, j = i & 127;
    float v0 = W[j * DD + 2 * kp];
    float v1 = W[j * DD + 2 * kp + 1];
    __nv_bfloat162 h = __float22bfloat162_rn(make_float2(v0, v1));
    float r0 = v0 - __bfloat162float(__low2bfloat16(h));
    float r1 = v1 - __bfloat162float(__high2bfloat16(h));
    __nv_bfloat162 l = __float22bfloat162_rn(make_float2(r0, r1));
    Wh[i] = *(unsigned*)&h;
    Wl[i] = *(unsigned*)&l;
}

// ---------------------------------------------------------------------------
// Tensor-core GEMM (3-term split-BF16, m16n8k16), A-rows pre-scaled by dinv:
//   Y[r,:] (fp16) = dinv[r] * ( X[r,:] @ W^T )
// Terms: ah*bh + al*bh + ah*bl  (al*bl ~ 2^-18, dropped)
// ---------------------------------------------------------------------------
#define MMA_BF16(C, A, B0, B1)                                                 \
    asm volatile("mma.sync.aligned.m16n8k16.row.col.f32.bf16.bf16.f32 "       \
                 "{%0,%1,%2,%3}, {%4,%5,%6,%7}, {%8,%9}, {%0,%1,%2,%3};"      \
                 : "+f"(C[0]), "+f"(C[1]), "+f"(C[2]), "+f"(C[3])             \
                 : "r"(A[0]), "r"(A[1]), "r"(A[2]), "r"(A[3]), "r"(B0), "r"(B1))

__device__ __forceinline__ void split_pack(float x0, float x1,
                                           unsigned& hi, unsigned& lo) {
    __nv_bfloat162 h = __float22bfloat162_rn(make_float2(x0, x1));
    float r0 = x0 - __bfloat162float(__low2bfloat16(h));
    float r1 = x1 - __bfloat162float(__high2bfloat16(h));
    __nv_bfloat162 l = __float22bfloat162_rn(make_float2(r0, r1));
    hi = *(unsigned*)&h;
    lo = *(unsigned*)&l;
}

__global__ __launch_bounds__(256) void k_gemm_tc(const float* __restrict__ X,
                                                 const unsigned* __restrict__ Wth,
                                                 const unsigned* __restrict__ Wtl,
                                                 __half* __restrict__ Y,
                                                 int rbase, int n) {
    __shared__ float    xs[128][36];    // fp32 A tile [row][k]
    __shared__ unsigned whp[16][136];   // bf16x2 k-pairs, [kpair][j], pad 136
    __shared__ unsigned wlp[16][136];

    const int tid  = threadIdx.x;
    const int warp = tid >> 5;
    const int lane = tid & 31;
    const int g    = lane >> 2;   // 0..7
    const int tig  = lane & 3;    // 0..3
    const int br   = rbase + blockIdx.x * 128;
    const int rb   = warp * 16;

    float c[16][4];
#pragma unroll
    for (int nt = 0; nt < 16; nt++)
#pragma unroll
        for (int q = 0; q < 4; q++) c[nt][q] = 0.0f;

    for (int kc = 0; kc < 128; kc += 32) {
        // A tile: 128x32 fp32, scaled by dinv[row]
#pragma unroll
        for (int j = 0; j < 4; j++) {
            int i = tid + j * 256;
            int r = i >> 3, kq = (i & 7) * 4;
            int row = br + r;
            float4 v = make_float4(0.f, 0.f, 0.f, 0.f);
            if (row < n) {
                float sc = g_dinv[row];
                v = *(const float4*)&X[(size_t)row * 128 + kc + kq];
                v.x *= sc; v.y *= sc; v.z *= sc; v.w *= sc;
            }
            *(float4*)&xs[r][kq] = v;
        }
        // W tiles: 16 kpairs x 128 cols of bf16x2 (uint), hi+lo
        {
            int kcp = kc >> 1;   // kpair base
#pragma unroll
            for (int j = 0; j < 2; j++) {
                int i = tid + j * 256;           // 0..511
                int kp = i >> 5, jq = (i & 31) * 4;
                *(uint4*)&whp[kp][jq] = *(const uint4*)&Wth[(kcp + kp) * 128 + jq];
                *(uint4*)&wlp[kp][jq] = *(const uint4*)&Wtl[(kcp + kp) * 128 + jq];
            }
        }
        __syncthreads();

#pragma unroll
        for (int ks = 0; ks < 32; ks += 16) {
            // A fragment: rows g, g+8; k = ks+2tig, +1 and ks+2tig+8, +9
            unsigned ah[4], al[4];
            {
                float x0 = xs[rb + g][ks + 2 * tig];
                float x1 = xs[rb + g][ks + 2 * tig + 1];
                float x2 = xs[rb + g + 8][ks + 2 * tig];
                float x3 = xs[rb + g + 8][ks + 2 * tig + 1];
                float x4 = xs[rb + g][ks + 2 * tig + 8];
                float x5 = xs[rb + g][ks + 2 * tig + 9];
                float x6 = xs[rb + g + 8][ks + 2 * tig + 8];
                float x7 = xs[rb + g + 8][ks + 2 * tig + 9];
                split_pack(x0, x1, ah[0], al[0]);
                split_pack(x2, x3, ah[1], al[1]);
                split_pack(x4, x5, ah[2], al[2]);
                split_pack(x6, x7, ah[3], al[3]);
            }
            const int kpb = ks >> 1;   // 0 or 8
#pragma unroll
            for (int nt = 0; nt < 16; nt++) {
                int col = nt * 8 + g;
                unsigned bh0 = whp[kpb + tig][col];
                unsigned bh1 = whp[kpb + 4 + tig][col];
                unsigned bl0 = wlp[kpb + tig][col];
                unsigned bl1 = wlp[kpb + 4 + tig][col];
                MMA_BF16(c[nt], ah, bh0, bh1);   // hi*hi
                MMA_BF16(c[nt], al, bh0, bh1);   // lo*hi
                MMA_BF16(c[nt], ah, bl0, bl1);   // hi*lo
            }
        }
        __syncthreads();
    }

    const int row0 = br + rb + g;
    const int row1 = row0 + 8;
#pragma unroll
    for (int nt = 0; nt < 16; nt++) {
        int col = nt * 8 + tig * 2;
        if (row0 < n)
            *(__half2*)&Y[(size_t)row0 * 128 + col] = __floats2half2_rn(c[nt][0], c[nt][1]);
        if (row1 < n)
            *(__half2*)&Y[(size_t)row1 * 128 + col] = __floats2half2_rn(c[nt][2], c[nt][3]);
    }
}

// ---------------------------------------------------------------------------
// Gather: 2 nodes per warp (16 lanes each), LDG.128 payload (16B fp16/lane).
//   O[d,:] = dinv[d] * ( H'[d,:] + sum_{s in N(d)} H'[s,:] ) + bias + P[d,:]
// ---------------------------------------------------------------------------
__device__ __forceinline__ void acc_u4(uint4 u, float acc[8]) {
    const __half2* hp = (const __half2*)&u;
#pragma unroll
    for (int j = 0; j < 4; j++) {
        float2 f = __half22float2(hp[j]);
        acc[2 * j]     += f.x;
        acc[2 * j + 1] += f.y;
    }
}

__global__ __launch_bounds__(256) void k_gather(const __half* __restrict__ H,
                                                const float* __restrict__ bias,
                                                const float4* __restrict__ P,
                                                float4* __restrict__ O,
                                                int off, int nchunk) {
    const int w    = (blockIdx.x * blockDim.x + threadIdx.x) >> 5;
    const int lane = threadIdx.x & 31;
    const int half = lane >> 4;
    const int sl   = lane & 15;
    const int d    = off + w * 2 + half;
    if (d >= off + nchunk) return;
    const unsigned hmask = 0xFFFFu << (half << 4);

    float acc[8];
    {
        uint4 u = *(const uint4*)(H + (size_t)d * 128 + sl * 8);
        const __half2* hp = (const __half2*)&u;
#pragma unroll
        for (int j = 0; j < 4; j++) {
            float2 f = __half22float2(hp[j]);
            acc[2 * j] = f.x; acc[2 * j + 1] = f.y;
        }
    }

    const int rp0 = __ldg(&g_rowptr[d]);
    const int cnt = __ldg(&g_rowptr[d + 1]) - rp0;

    for (int base = 0; base < cnt; base += 16) {
        int m = cnt - base; if (m > 16) m = 16;
        int idx = (sl < m) ? __ldg(&g_col[rp0 + base + sl]) : 0;
        int k = 0;
        for (; k + 8 <= m; k += 8) {
            int s[8]; uint4 u[8];
#pragma unroll
            for (int q = 0; q < 8; q++) s[q] = __shfl_sync(hmask, idx, k + q, 16);
#pragma unroll
            for (int q = 0; q < 8; q++) u[q] = *(const uint4*)(H + (size_t)s[q] * 128 + sl * 8);
#pragma unroll
            for (int q = 0; q < 8; q++) acc_u4(u[q], acc);
        }
        for (; k < m; k++) {
            int s0 = __shfl_sync(hmask, idx, k, 16);
            uint4 u = *(const uint4*)(H + (size_t)s0 * 128 + sl * 8);
            acc_u4(u, acc);
        }
    }

    const float dd = g_dinv[d];
    float4 b0 = ((const float4*)bias)[sl * 2];
    float4 b1 = ((const float4*)bias)[sl * 2 + 1];
    float4 p0 = P[(size_t)d * 32 + sl * 2];
    float4 p1 = P[(size_t)d * 32 + sl * 2 + 1];
    float4 o0, o1;
    o0.x = dd * acc[0] + b0.x + p0.x;
    o0.y = dd * acc[1] + b0.y + p0.y;
    o0.z = dd * acc[2] + b0.z + p0.z;
    o0.w = dd * acc[3] + b0.w + p0.w;
    o1.x = dd * acc[4] + b1.x + p1.x;
    o1.y = dd * acc[5] + b1.y + p1.y;
    o1.z = dd * acc[6] + b1.z + p1.z;
    o1.w = dd * acc[7] + b1.w + p1.w;
    O[(size_t)d * 32 + sl * 2]     = o0;
    O[(size_t)d * 32 + sl * 2 + 1] = o1;
}

// ---------------------------------------------------------------------------
// Launch. Submission order puts gemm1 at kernel-launch slot 4 (the slot the
// harness ncu capture profiles) for evidence next round.
// ---------------------------------------------------------------------------
extern "C" void kernel_launch(void* const* d_in, const int* in_sizes, int n_in,
                              void* d_out, int out_size) {
    const float* x  = (const float*)d_in[0];
    const int*   ei = (const int*)  d_in[1];
    const float* pf = (const float*)d_in[2];
    const float* pl = (const float*)d_in[3];
    const float* W1 = (const float*)d_in[4];
    const float* b1 = (const float*)d_in[5];
    const float* W2 = (const float*)d_in[6];
    const float* b2 = (const float*)d_in[7];
    float* out = (float*)d_out;

    const int n = in_sizes[0] / DD;
    const int E = in_sizes[1] / 2;
    const int* src = ei;
    const int* dst = ei + E;

    __half* ph1; __half* ph2; float* pa;
    unsigned* w1h; unsigned* w1l; unsigned* w2h; unsigned* w2l;
    cudaGetSymbolAddress((void**)&ph1, g_h1);
    cudaGetSymbolAddress((void**)&ph2, g_h2);
    cudaGetSymbolAddress((void**)&pa, g_a);
    cudaGetSymbolAddress((void**)&w1h, g_w1h);
    cudaGetSymbolAddress((void**)&w1l, g_w1l);
    cudaGetSymbolAddress((void**)&w2h, g_w2h);
    cudaGetSymbolAddress((void**)&w2l, g_w2l);

    static cudaStream_t s2 = nullptr;
    static cudaEvent_t evFork = nullptr, evDinv = nullptr, evJoin = nullptr,
                       evA = nullptr, evG2A = nullptr;
    if (!s2) {
        cudaStreamCreateWithFlags(&s2, cudaStreamNonBlocking);
        cudaEventCreateWithFlags(&evFork, cudaEventDisableTiming);
        cudaEventCreateWithFlags(&evDinv, cudaEventDisableTiming);
        cudaEventCreateWithFlags(&evJoin, cudaEventDisableTiming);
        cudaEventCreateWithFlags(&evA, cudaEventDisableTiming);
        cudaEventCreateWithFlags(&evG2A, cudaEventDisableTiming);
    }

    const int T = 256;
    const int nb1024 = (n + 1023) / 1024;
    const int splitw_blocks = ((DD / 2) * DD + T - 1) / T;
    const int e4blocks = ((E + 3) / 4 + T - 1) / T;

    const int nA = (((n + 1) / 2 + 127) / 128) * 128;
    const int nB = n - nA;

    // Slot 1: split W1 on s2 (no deps).
    cudaEventRecord(evFork, 0);
    cudaStreamWaitEvent(s2, evFork, 0);
    k_split_w<<<splitw_blocks, T, 0, s2>>>(W1, w1h, w1l);

    // Slots 2-3 (main): degrees + dinv.
    k_count<<<e4blocks, T>>>(dst, E);
    k_scan1<<<nb1024, 1024>>>(n);   // dinv + tile-local rowptr; last read of cnt
    cudaEventRecord(evDinv, 0);

    // Slot 4 (s2): gemm1 -> h1  [PROFILED SLOT]
    cudaStreamWaitEvent(s2, evDinv, 0);
    k_gemm_tc<<<(n + 127) / 128, T, 0, s2>>>(x, w1h, w1l, ph1, 0, n);
    cudaEventRecord(evJoin, s2);
    // Slot 5 (s2): split W2 (needed only by gemm2).
    k_split_w<<<splitw_blocks, T, 0, s2>>>(W2, w2h, w2l);

    // Main: re-zero cnt for next call; finish CSR.
    k_zero_cnt<<<(n + T - 1) / T, T>>>(n);
    k_scan2<<<1, 1024>>>(nb1024);
    k_scan3<<<(n + 1 + 1023) / 1024, 1024>>>(n, E);
    k_scatter<<<e4blocks, T>>>(src, dst, E);

    cudaStreamWaitEvent(0, evJoin, 0);

    // gather1(A) -> pa[A]; gemm2(A): pa[A] -> h2[A] on s2, overlapped with
    // gather1(B) (reads h1, which is never overwritten).
    k_gather<<<(nA + 15) / 16, T>>>(ph1, b1, (const float4*)pf, (float4*)pa, 0, nA);
    cudaEventRecord(evA, 0);
    cudaStreamWaitEvent(s2, evA, 0);
    k_gemm_tc<<<nA / 128, T, 0, s2>>>(pa, w2h, w2l, ph2, 0, nA);
    cudaEventRecord(evG2A, s2);

    k_gather<<<(nB + 15) / 16, T>>>(ph1, b1, (const float4*)pf, (float4*)pa, nA, nB);
    k_gemm_tc<<<(nB + 127) / 128, T>>>(pa, w2h, w2l, ph2, nA, n);
    cudaStreamWaitEvent(0, evG2A, 0);

    // Final gather over all nodes reads h2.
    k_gather<<<(n + 15) / 16, T>>>(ph2, b2, (const float4*)pl, (float4*)out, 0, n);
}